// round 1
// baseline (speedup 1.0000x reference)
#include <cuda_runtime.h>
#include <cuda_bf16.h>
#include <cstdint>

// FSQ: q = round(4*tanh( W @ LayerNorm(x) )), folded into a single pass:
//   logit_n = rstd * (dot(x, gamma*W_n) - mu * s_n) + b_n
// One block = 32 rows (8 warps x 4 rows). W' kept in smem as f32x2 K-pairs,
// padded to 9 pairs/row (72B) for conflict-free LDS.64.

typedef unsigned long long u64;

__device__ __forceinline__ void fma2(u64 &d, u64 a, u64 b) {
    asm("fma.rn.f32x2 %0, %1, %2, %0;" : "+l"(d) : "l"(a), "l"(b));
}
__device__ __forceinline__ void add2(u64 &d, u64 a) {
    asm("add.rn.f32x2 %0, %0, %1;" : "+l"(d) : "l"(a));
}
__device__ __forceinline__ u64 pack2(float a, float b) {
    u64 r;
    asm("mov.b64 %0, {%1, %2};" : "=l"(r) : "r"(__float_as_uint(a)), "r"(__float_as_uint(b)));
    return r;
}
__device__ __forceinline__ float2 up2(u64 v) {
    unsigned a, b;
    asm("mov.b64 {%0, %1}, %2;" : "=r"(a), "=r"(b) : "l"(v));
    return make_float2(__uint_as_float(a), __uint_as_float(b));
}
__device__ __forceinline__ float pairsum(u64 v) {
    float2 f = up2(v);
    return f.x + f.y;
}

// rintf(4*tanh(x)), fast-math-proof (fmaf/rcp.rn/sqrt.rn only).
__device__ __forceinline__ float tanh4_round(float x) {
    float ax = fabsf(x);
    float r;
    if (ax >= 1.5f) {
        // 4*tanh(1.5) = 3.6206 -> rounds to 4; monotone beyond.
        r = 4.0f;
    } else {
        // exp(2*ax) via exp2 split, polynomial e^y on y in [-ln2/2, ln2/2]
        const float T2L = 2.8853900817779268f;   // 2*log2(e)
        float t = ax * T2L;                      // in [0, 4.33]
        float k = rintf(t);
        float f = t - k;                         // [-0.5, 0.5]
        float y = f * 0.6931471805599453f;       // [-0.3466, 0.3466]
        float p = 1.9841269841e-4f;              // 1/5040
        p = fmaf(p, y, 1.3888888888e-3f);        // 1/720
        p = fmaf(p, y, 8.3333333333e-3f);        // 1/120
        p = fmaf(p, y, 4.1666666667e-2f);        // 1/24
        p = fmaf(p, y, 1.6666666667e-1f);        // 1/6
        p = fmaf(p, y, 0.5f);
        p = fmaf(p, y, 1.0f);
        p = fmaf(p, y, 1.0f);
        float scale = __int_as_float(((int)k + 127) << 23);
        float e = p * scale;                     // exp(2*ax)
        float num = e - 1.0f;
        float den = e + 1.0f;
        float th = num * __frcp_rn(den);         // tanh(ax)
        r = rintf(4.0f * th);
    }
    return copysignf(r, x);
}

static const int D       = 1024;
static const int PAIRS   = 512;   // D/2
static const int NL      = 8;
static const int WPAD    = 9;     // f32x2 per pair-row (8 used + 1 pad) -> 72B stride
static const int ROWS_PB = 32;    // rows per block
static const int R       = 4;     // rows per warp

__global__ void __launch_bounds__(256, 2)
fsq_kernel(const float* __restrict__ x, const float* __restrict__ gamma,
           const float* __restrict__ beta, const float* __restrict__ W,
           float* __restrict__ out, int rows)
{
    __shared__ u64   sWp[PAIRS * WPAD];    // 36864 B: W'[pair][n] as f32x2
    __shared__ float sStats[ROWS_PB][12];  // per-row: sum, sumsq, 8 dots
    __shared__ float sRed[8][16];          // s/b block reduction scratch
    __shared__ float sSB[16];              // s[0..7], b[0..7]

    const int tid  = threadIdx.x;
    const int lane = tid & 31;
    const int wid  = tid >> 5;

    // ---------------- prep: W' = gamma*W into smem; s_n, b_n ----------------
    float sP[NL], bP[NL];
#pragma unroll
    for (int n = 0; n < NL; n++) { sP[n] = 0.0f; bP[n] = 0.0f; }

    const u64* W2 = (const u64*)W;      // [8][512] pairs
    const u64* g2 = (const u64*)gamma;  // [512]
    const u64* e2 = (const u64*)beta;   // [512]

#pragma unroll
    for (int i = 0; i < 2; i++) {
        int p = tid + i * 256;
        float2 g = up2(g2[p]);
        float2 b = up2(e2[p]);
#pragma unroll
        for (int n = 0; n < NL; n++) {
            float2 w = up2(W2[n * PAIRS + p]);
            float pl = g.x * w.x;
            float ph = g.y * w.y;
            sWp[p * WPAD + n] = pack2(pl, ph);
            sP[n] += pl + ph;
            bP[n] += b.x * w.x + b.y * w.y;
        }
    }
    // deterministic warp tree reduce
#pragma unroll
    for (int o = 16; o; o >>= 1) {
#pragma unroll
        for (int n = 0; n < NL; n++) {
            sP[n] += __shfl_xor_sync(0xffffffffu, sP[n], o);
            bP[n] += __shfl_xor_sync(0xffffffffu, bP[n], o);
        }
    }
    if (lane == 0) {
#pragma unroll
        for (int n = 0; n < NL; n++) {
            sRed[wid][n]     = sP[n];
            sRed[wid][8 + n] = bP[n];
        }
    }
    __syncthreads();
    if (tid < 16) {
        float v = 0.0f;
#pragma unroll
        for (int w = 0; w < 8; w++) v += sRed[w][tid];
        sSB[tid] = v;
    }
    __syncthreads();

    // ---------------- main: 4 rows per warp, single pass ----------------
    const int rowBase = blockIdx.x * ROWS_PB + wid * R;
    const u64* xr[R];
#pragma unroll
    for (int r = 0; r < R; r++) {
        int ri = rowBase + r;
        if (ri >= rows) ri = rows - 1;   // safe clamp (never hit for 65536 rows)
        xr[r] = (const u64*)x + (size_t)ri * PAIRS;
    }

    u64 dots[R][NL];
    u64 sum2[R], ssq2[R];
#pragma unroll
    for (int r = 0; r < R; r++) {
        sum2[r] = 0ull; ssq2[r] = 0ull;
#pragma unroll
        for (int n = 0; n < NL; n++) dots[r][n] = 0ull;
    }

#pragma unroll 2
    for (int it = 0; it < 16; it++) {
        int p = (it << 5) + lane;
        u64 xv[R];
#pragma unroll
        for (int r = 0; r < R; r++) xv[r] = __ldcs(&xr[r][p]);  // streaming loads
#pragma unroll
        for (int r = 0; r < R; r++) {
            add2(sum2[r], xv[r]);
            fma2(ssq2[r], xv[r], xv[r]);
        }
        const u64* wrow = &sWp[p * WPAD];
#pragma unroll
        for (int n = 0; n < NL; n++) {
            u64 w = wrow[n];
#pragma unroll
            for (int r = 0; r < R; r++) fma2(dots[r][n], xv[r], w);
        }
    }

    // ---------------- reduce + stash stats ----------------
#pragma unroll
    for (int r = 0; r < R; r++) {
        float s = pairsum(sum2[r]);
        float q = pairsum(ssq2[r]);
        float dv[NL];
#pragma unroll
        for (int n = 0; n < NL; n++) dv[n] = pairsum(dots[r][n]);
#pragma unroll
        for (int o = 16; o; o >>= 1) {
            s += __shfl_xor_sync(0xffffffffu, s, o);
            q += __shfl_xor_sync(0xffffffffu, q, o);
#pragma unroll
            for (int n = 0; n < NL; n++)
                dv[n] += __shfl_xor_sync(0xffffffffu, dv[n], o);
        }
        if (lane == 0) {
            sStats[wid * R + r][0] = s;
            sStats[wid * R + r][1] = q;
#pragma unroll
            for (int n = 0; n < NL; n++) sStats[wid * R + r][2 + n] = dv[n];
        }
    }
    __syncthreads();

    // ---------------- tail: 256 threads = 32 rows x 8 levels ----------------
    {
        int rr = tid >> 3;
        int n  = tid & 7;
        int orow = blockIdx.x * ROWS_PB + rr;
        if (orow < rows) {
            float s  = sStats[rr][0];
            float q  = sStats[rr][1];
            float dv = sStats[rr][2 + n];
            float mu   = s * (1.0f / 1024.0f);
            float var  = fmaf(-mu, mu, q * (1.0f / 1024.0f));
            float rstd = __frcp_rn(__fsqrt_rn(var + 1e-5f));
            float lg   = fmaf(rstd, fmaf(-mu, sSB[n], dv), sSB[8 + n]);
            out[(size_t)orow * NL + n] = tanh4_round(lg);
        }
    }
}

extern "C" void kernel_launch(void* const* d_in, const int* in_sizes, int n_in,
                              void* d_out, int out_size)
{
    const float* x     = (const float*)d_in[0];  // [8,8192,1024]
    const float* gamma = (const float*)d_in[1];  // [1024]
    const float* beta  = (const float*)d_in[2];  // [1024]
    const float* W     = (const float*)d_in[3];  // [8,1024]
    float* out = (float*)d_out;                  // [8,8192,8]

    int rows = in_sizes[0] / D;
    int grid = (rows + ROWS_PB - 1) / ROWS_PB;
    fsq_kernel<<<grid, 256>>>(x, gamma, beta, W, out, rows);
}